// round 8
// baseline (speedup 1.0000x reference)
#include <cuda_runtime.h>
#include <cuda_bf16.h>
#include <cstdint>

// CIF: continuous integrate-and-fire. B=32, T=2000, H=512, L=256, thresh=0.95
//
// Kernel A (32 + 1024 CTAs x 256 threads):
//   CTAs 0..31  : per-row scan — dp row sum -> scale; serial minimal chain on
//                 thread 0 (FADD -> ISETP(bits) -> SEL, int-select; bit-exact);
//                 checkpoints every 32 steps; two bit-exact replay passes emit
//                 fire records (fpos/rem/cur).
//   CTAs 32+    : stream all of hidden (131 MB) through L2 (~126 MB) so the
//                 gather hits L2 instead of DRAM. Runs concurrently with the
//                 latency-bound scan -> free.
// Kernel B (grid (L,B) x 128): interior weights recomputed as alphas[t]*scale
//   (bit-identical FMUL), segment-end fire frame uses cur[k], carry rem[k-1].

#define CIF_B 32
#define CIF_T 2000
#define CIF_H 512
#define CIF_L 256
#define CIF_THRESH 0.95f

#define CHUNK 32
#define NCHUNK 63                 // 63*32 = 2016 >= 2000 (zero-padded)
#define T_PAD (NCHUNK * CHUNK)

#define PRE_CTAS 1024             // prefetch CTAs (CTAs 32 .. 32+1023)
#define H4_TOTAL (CIF_B * CIF_T * CIF_H / 4)   // hidden in float4s = 8.192M

// Scratch (allocation-free contract)
__device__ int   g_fpos[CIF_B * CIF_L];
__device__ float g_rem [CIF_B * CIF_L];
__device__ float g_cur [CIF_B * CIF_L];
__device__ float g_scale[CIF_B];
__device__ int   g_nf[CIF_B];
__device__ float g_sink;          // keeps prefetch loads alive

// minimal CIF step: chain = FADD -> ISETP(bits, data-consumed) -> SEL (int)
// fire <=> (signed)bits(i2) >= bits(0.95f); valid since i2 > -0.06 > -0.95f
// (no signed wrap, negatives compare below threshold). Selected values are the
// exact floats i2 and i2-1.0f (Sterbenz-exact), so the trajectory is
// bit-identical to the reference recurrence.
__device__ __forceinline__ void cif_step_min(float a, float& integ)
{
    float i2, sub;
    asm("{\n\t"
        ".reg .pred p;\n\t"
        ".reg .b32  bi, bs, bo;\n\t"
        "add.f32 %0, %2, %3;\n\t"               // i2 = integ + a
        "add.f32 %1, %0, 0fBF800000;\n\t"       // sub = i2 - 1.0f (off-chain)
        "mov.b32 bi, %0;\n\t"
        "mov.b32 bs, %1;\n\t"
        "setp.ge.s32 p, bi, 1064514355;\n\t"    // bits(i2) >= bits(0.95f), signed
        "selp.b32 bo, bs, bi, p;\n\t"           // int select
        "mov.b32 %2, bo;\n\t"                   // integ = fire ? sub : i2
        "}"
        : "=f"(i2), "=f"(sub), "+f"(integ)
        : "f"(a));
}

// ---------------------------------------------------------------------------
// Kernel A: scan CTAs + hidden->L2 prefetch CTAs
// ---------------------------------------------------------------------------
__global__ __launch_bounds__(256, 1)
void cif_scan_kernel(const float* __restrict__ alphas,
                     const int* __restrict__ target_lengths,
                     const float4* __restrict__ hidden4)
{
    const int tid = threadIdx.x;

    // ---------------- prefetch CTAs: stream hidden through L2 ----------------
    if (blockIdx.x >= CIF_B) {
        const int pid = blockIdx.x - CIF_B;
        float acc = 0.0f;
        // grid-stride over all of hidden; 8.192M float4s / (1024*256) = 32 iters
        for (int i = pid * 256 + tid; i < H4_TOTAL; i += PRE_CTAS * 256) {
            float4 v = hidden4[i];
            acc += v.x + v.y + v.z + v.w;
        }
        if (acc == 1.23456789e38f)   // never true; defeats DCE
            g_sink = acc;
        return;
    }

    // ---------------- scan CTAs (one per batch row) ----------------
    __shared__ __align__(16) float s_a[T_PAD];   // scaled alphas, zero-padded
    __shared__ float  s_i0[NCHUNK];              // chunk-start integ
    __shared__ int    s_cnt[NCHUNK];             // fires per chunk
    __shared__ int    s_off[NCHUNK];             // token offset per chunk
    __shared__ int    s_fp[CIF_L];
    __shared__ float  s_rm[CIF_L];
    __shared__ float  s_cur[CIF_L];
    __shared__ double s_red[256];
    __shared__ float  s_scale;
    __shared__ int    s_nf;

    const int b = blockIdx.x;
    const float* arow = alphas + b * CIF_T;

    // --- deterministic double-precision row sum ---
    double acc = 0.0;
    for (int t = tid; t < CIF_T; t += 256)
        acc += (double)arow[t];
    s_red[tid] = acc;
    __syncthreads();
    for (int off = 128; off > 0; off >>= 1) {
        if (tid < off) s_red[tid] += s_red[tid + off];
        __syncthreads();
    }
    if (tid == 0) {
        float sc = (float)target_lengths[b] / (float)s_red[0];
        s_scale = sc;
        g_scale[b] = sc;
    }
    __syncthreads();

    // --- stage scaled alphas (fp32 mul, like reference); zero pad ---
    const float scale = s_scale;
    for (int t = tid; t < T_PAD; t += 256)
        s_a[t] = (t < CIF_T) ? arow[t] * scale : 0.0f;
    __syncthreads();

    // --- serial minimal chain: only integ; checkpoint every 32 steps ---
    if (tid == 0) {
        float integ = 0.0f;
        const float4* a4 = reinterpret_cast<const float4*>(s_a);
        #pragma unroll 1
        for (int c = 0; c < NCHUNK; ++c) {
            s_i0[c] = integ;
            #pragma unroll
            for (int q = 0; q < CHUNK / 4; ++q) {
                float4 av = a4[c * (CHUNK / 4) + q];
                cif_step_min(av.x, integ);
                cif_step_min(av.y, integ);
                cif_step_min(av.z, integ);
                cif_step_min(av.w, integ);
            }
        }
    }
    __syncthreads();

    // --- replay pass 1: count fires per chunk (bit-exact) ---
    if (tid < NCHUNK) {
        float integ = s_i0[tid];
        int cnt = 0;
        const int tbase = tid * CHUNK;
        #pragma unroll
        for (int j = 0; j < CHUNK; ++j) {
            float a    = s_a[tbase + j];
            float i2   = integ + a;
            bool  fire = (i2 >= CIF_THRESH);
            integ = fire ? (i2 - 1.0f) : i2;
            cnt  += fire ? 1 : 0;
        }
        s_cnt[tid] = cnt;
    }
    __syncthreads();

    // --- prefix sum over chunks ---
    if (tid == 0) {
        int accn = 0;
        #pragma unroll
        for (int c = 0; c < NCHUNK; ++c) {
            s_off[c] = accn;
            accn += s_cnt[c];
        }
        s_nf = accn;
        g_nf[b] = accn;
    }
    __syncthreads();

    // --- replay pass 2: emit records (bit-exact values) ---
    if (tid < NCHUNK) {
        float integ = s_i0[tid];
        int k = s_off[tid];
        const int tbase = tid * CHUNK;
        #pragma unroll
        for (int j = 0; j < CHUNK; ++j) {
            float a    = s_a[tbase + j];
            float i2   = integ + a;
            bool  fire = (i2 >= CIF_THRESH);
            float cur  = 1.0f - integ;            // dist_completion (old integ)
            if (fire) {
                if (k < CIF_L) {
                    s_fp[k]  = tbase + j;
                    s_rm[k]  = a - cur;           // remainds
                    s_cur[k] = cur;
                }
                k++;
            }
            integ = fire ? (i2 - 1.0f) : i2;
        }
    }
    __syncthreads();

    // --- flush valid records ---
    int nf_tot = s_nf < CIF_L ? s_nf : CIF_L;
    if (tid < nf_tot) {
        g_fpos[b * CIF_L + tid] = s_fp[tid];
        g_rem [b * CIF_L + tid] = s_rm[tid];
        g_cur [b * CIF_L + tid] = s_cur[tid];
    }
}

// ---------------------------------------------------------------------------
// Kernel B: segmented weighted gather (grid (L,B), 128 threads; float4/thread)
// ---------------------------------------------------------------------------
__global__ __launch_bounds__(128, 12)
void cif_gather_kernel(const float* __restrict__ hidden,
                       const float* __restrict__ alphas,
                       float* __restrict__ out)
{
    const int k   = blockIdx.x;
    const int b   = blockIdx.y;
    const int tid = threadIdx.x;
    const int HS  = CIF_H / 4;

    float4* out4 = reinterpret_cast<float4*>(out + ((size_t)(b * CIF_L + k)) * CIF_H) + tid;

    int nf = g_nf[b];
    nf = nf < CIF_L ? nf : CIF_L;
    if (k >= nf) {
        *out4 = make_float4(0.f, 0.f, 0.f, 0.f);
        return;
    }

    const float   scale = g_scale[b];
    const int     te    = g_fpos[b * CIF_L + k];
    const float*  arow  = alphas + b * CIF_T;
    const float4* h4    = reinterpret_cast<const float4*>(hidden + (size_t)b * CIF_T * CIF_H) + tid;

    float4 accv;
    int t0;
    if (k == 0) {
        t0 = 0;
        accv = make_float4(0.f, 0.f, 0.f, 0.f);
    } else {
        const int   ts = g_fpos[b * CIF_L + k - 1];
        const float wt = g_rem[b * CIF_L + k - 1];
        float4 hv = __ldg(h4 + (size_t)ts * HS);
        accv = make_float4(wt * hv.x, wt * hv.y, wt * hv.z, wt * hv.w);
        t0 = ts + 1;
    }

    // interior frames t0 .. te-1 : weight = alphas[t]*scale (bit-identical)
    int t = t0;
    for (; t + 4 <= te; t += 4) {
        float w0 = __ldg(arow + t)     * scale;
        float w1 = __ldg(arow + t + 1) * scale;
        float w2 = __ldg(arow + t + 2) * scale;
        float w3 = __ldg(arow + t + 3) * scale;
        float4 h0 = __ldg(h4 + (size_t)(t    ) * HS);
        float4 h1 = __ldg(h4 + (size_t)(t + 1) * HS);
        float4 h2 = __ldg(h4 + (size_t)(t + 2) * HS);
        float4 h3 = __ldg(h4 + (size_t)(t + 3) * HS);
        accv.x = fmaf(w0, h0.x, accv.x); accv.y = fmaf(w0, h0.y, accv.y);
        accv.z = fmaf(w0, h0.z, accv.z); accv.w = fmaf(w0, h0.w, accv.w);
        accv.x = fmaf(w1, h1.x, accv.x); accv.y = fmaf(w1, h1.y, accv.y);
        accv.z = fmaf(w1, h1.z, accv.z); accv.w = fmaf(w1, h1.w, accv.w);
        accv.x = fmaf(w2, h2.x, accv.x); accv.y = fmaf(w2, h2.y, accv.y);
        accv.z = fmaf(w2, h2.z, accv.z); accv.w = fmaf(w2, h2.w, accv.w);
        accv.x = fmaf(w3, h3.x, accv.x); accv.y = fmaf(w3, h3.y, accv.y);
        accv.z = fmaf(w3, h3.z, accv.z); accv.w = fmaf(w3, h3.w, accv.w);
    }
    for (; t < te; ++t) {
        float  w  = __ldg(arow + t) * scale;
        float4 hv = __ldg(h4 + (size_t)t * HS);
        accv.x = fmaf(w, hv.x, accv.x);
        accv.y = fmaf(w, hv.y, accv.y);
        accv.z = fmaf(w, hv.z, accv.z);
        accv.w = fmaf(w, hv.w, accv.w);
    }
    // segment-end fire frame: weight = cur
    {
        float  wc = g_cur[b * CIF_L + k];
        float4 hv = __ldg(h4 + (size_t)te * HS);
        accv.x = fmaf(wc, hv.x, accv.x);
        accv.y = fmaf(wc, hv.y, accv.y);
        accv.z = fmaf(wc, hv.z, accv.z);
        accv.w = fmaf(wc, hv.w, accv.w);
    }
    *out4 = accv;
}

// ---------------------------------------------------------------------------
extern "C" void kernel_launch(void* const* d_in, const int* in_sizes, int n_in,
                              void* d_out, int out_size)
{
    const float* hidden = (const float*)d_in[0];
    const float* alphas = (const float*)d_in[1];
    const int*   tlen   = (const int*)d_in[2];
    float* out = (float*)d_out;

    cif_scan_kernel<<<CIF_B + PRE_CTAS, 256>>>(alphas, tlen,
                                               (const float4*)hidden);
    dim3 grid(CIF_L, CIF_B);
    cif_gather_kernel<<<grid, 128>>>(hidden, alphas, out);
}

// round 10
// speedup vs baseline: 1.0390x; 1.0390x over previous
#include <cuda_runtime.h>
#include <cuda_bf16.h>
#include <cstdint>

// CIF: continuous integrate-and-fire. B=32, T=2000, H=512, L=256, thresh=0.95
//
// Scan (32 CTAs x 256 threads, one per batch row):
//   1. double-precision row sum -> fp32 scale
//   2. serial minimal chain on thread 0: per 32-step chunk, preload all 8
//      float4 alphas into REGISTERS first, then run 32 register-only steps
//      (FADD -> FSETP -> FSEL pred-as-data; 12-cyc chain, smem off-chain);
//      checkpoint integ per chunk
//   3. replay pass 1 (63 threads): bit-exact fire counts per chunk
//   4. prefix sum -> token offsets; replay pass 2 writes fpos/rem/cur
// Gather (grid (L,B) x 128): interior weights = alphas[t]*scale (bit-identical
//   FMUL), segment-end fire frame uses cur[k], carry frame uses rem[k-1].
//
// Launch pattern {noop, scan, gather, noop} puts the SCAN kernel at ncu's
// skip-5-capture-1 slot (launch #6) for direct profiling.

#define CIF_B 32
#define CIF_T 2000
#define CIF_H 512
#define CIF_L 256
#define CIF_THRESH 0.95f

#define CHUNK 32
#define NCHUNK 63                 // 63*32 = 2016 >= 2000 (zero-padded)
#define T_PAD (NCHUNK * CHUNK)

// Scratch (allocation-free contract)
__device__ int   g_fpos[CIF_B * CIF_L];
__device__ float g_rem [CIF_B * CIF_L];
__device__ float g_cur [CIF_B * CIF_L];
__device__ float g_scale[CIF_B];
__device__ int   g_nf[CIF_B];

// minimal CIF step: FADD -> FSETP -> FSEL (pred-as-data, 4-cyc classes)
__device__ __forceinline__ void cif_step_min(float a, float& integ)
{
    float i2, sub;
    asm("{\n\t"
        ".reg .pred p;\n\t"
        "add.f32 %0, %2, %3;\n\t"               // i2 = integ + a
        "setp.ge.f32 p, %0, 0f3F733333;\n\t"    // fire = i2 >= 0.95f
        "add.f32 %1, %0, 0fBF800000;\n\t"       // sub = i2 - 1.0f (Sterbenz-exact)
        "selp.f32 %2, %1, %0, p;\n\t"           // integ = fire ? sub : i2
        "}"
        : "=f"(i2), "=f"(sub), "+f"(integ)
        : "f"(a));
}

__global__ void cif_noop_kernel() {}

// ---------------------------------------------------------------------------
// Kernel A: rescale + register-fed serial scan + two-pass reconstruction
// ---------------------------------------------------------------------------
__global__ __launch_bounds__(256, 1)
void cif_scan_kernel(const float* __restrict__ alphas,
                     const int* __restrict__ target_lengths)
{
    __shared__ __align__(16) float s_a[T_PAD];   // scaled alphas, zero-padded
    __shared__ float  s_i0[NCHUNK];              // chunk-start integ
    __shared__ int    s_cnt[NCHUNK];             // fires per chunk
    __shared__ int    s_off[NCHUNK];             // token offset per chunk
    __shared__ int    s_fp[CIF_L];
    __shared__ float  s_rm[CIF_L];
    __shared__ float  s_cur[CIF_L];
    __shared__ double s_red[256];
    __shared__ float  s_scale;
    __shared__ int    s_nf;

    const int b   = blockIdx.x;
    const int tid = threadIdx.x;
    const float* arow = alphas + b * CIF_T;

    // --- deterministic double-precision row sum ---
    double acc = 0.0;
    for (int t = tid; t < CIF_T; t += 256)
        acc += (double)arow[t];
    s_red[tid] = acc;
    __syncthreads();
    for (int off = 128; off > 0; off >>= 1) {
        if (tid < off) s_red[tid] += s_red[tid + off];
        __syncthreads();
    }
    if (tid == 0) {
        float sc = (float)target_lengths[b] / (float)s_red[0];
        s_scale = sc;
        g_scale[b] = sc;
    }
    __syncthreads();

    // --- stage scaled alphas (fp32 mul, like reference); zero pad ---
    const float scale = s_scale;
    for (int t = tid; t < T_PAD; t += 256)
        s_a[t] = (t < CIF_T) ? arow[t] * scale : 0.0f;
    __syncthreads();

    // --- serial chain: preload chunk into registers, then register-only steps ---
    if (tid == 0) {
        float integ = 0.0f;
        const float4* a4 = reinterpret_cast<const float4*>(s_a);
        #pragma unroll 1
        for (int c = 0; c < NCHUNK; ++c) {
            s_i0[c] = integ;
            float4 v[CHUNK / 4];
            #pragma unroll
            for (int q = 0; q < CHUNK / 4; ++q)        // 8 LDS.128 batched
                v[q] = a4[c * (CHUNK / 4) + q];
            #pragma unroll
            for (int q = 0; q < CHUNK / 4; ++q) {      // 32 register-only steps
                cif_step_min(v[q].x, integ);
                cif_step_min(v[q].y, integ);
                cif_step_min(v[q].z, integ);
                cif_step_min(v[q].w, integ);
            }
        }
    }
    __syncthreads();

    // --- replay pass 1: count fires per chunk (bit-exact) ---
    if (tid < NCHUNK) {
        float integ = s_i0[tid];
        int cnt = 0;
        const int tbase = tid * CHUNK;
        #pragma unroll
        for (int j = 0; j < CHUNK; ++j) {
            float a    = s_a[tbase + j];
            float i2   = integ + a;
            bool  fire = (i2 >= CIF_THRESH);
            integ = fire ? (i2 - 1.0f) : i2;
            cnt  += fire ? 1 : 0;
        }
        s_cnt[tid] = cnt;
    }
    __syncthreads();

    // --- prefix sum over chunks ---
    if (tid == 0) {
        int accn = 0;
        #pragma unroll
        for (int c = 0; c < NCHUNK; ++c) {
            s_off[c] = accn;
            accn += s_cnt[c];
        }
        s_nf = accn;
        g_nf[b] = accn;
    }
    __syncthreads();

    // --- replay pass 2: emit records (bit-exact values) ---
    if (tid < NCHUNK) {
        float integ = s_i0[tid];
        int k = s_off[tid];
        const int tbase = tid * CHUNK;
        #pragma unroll
        for (int j = 0; j < CHUNK; ++j) {
            float a    = s_a[tbase + j];
            float i2   = integ + a;
            bool  fire = (i2 >= CIF_THRESH);
            float cur  = 1.0f - integ;            // dist_completion (old integ)
            if (fire) {
                if (k < CIF_L) {
                    s_fp[k]  = tbase + j;
                    s_rm[k]  = a - cur;           // remainds
                    s_cur[k] = cur;
                }
                k++;
            }
            integ = fire ? (i2 - 1.0f) : i2;
        }
    }
    __syncthreads();

    // --- flush valid records ---
    int nf_tot = s_nf < CIF_L ? s_nf : CIF_L;
    if (tid < nf_tot) {
        g_fpos[b * CIF_L + tid] = s_fp[tid];
        g_rem [b * CIF_L + tid] = s_rm[tid];
        g_cur [b * CIF_L + tid] = s_cur[tid];
    }
}

// ---------------------------------------------------------------------------
// Kernel B: segmented weighted gather (grid (L,B), 128 threads; float4/thread)
// ---------------------------------------------------------------------------
__global__ __launch_bounds__(128, 12)
void cif_gather_kernel(const float* __restrict__ hidden,
                       const float* __restrict__ alphas,
                       float* __restrict__ out)
{
    const int k   = blockIdx.x;
    const int b   = blockIdx.y;
    const int tid = threadIdx.x;
    const int HS  = CIF_H / 4;

    float4* out4 = reinterpret_cast<float4*>(out + ((size_t)(b * CIF_L + k)) * CIF_H) + tid;

    int nf = g_nf[b];
    nf = nf < CIF_L ? nf : CIF_L;
    if (k >= nf) {
        *out4 = make_float4(0.f, 0.f, 0.f, 0.f);
        return;
    }

    const float   scale = g_scale[b];
    const int     te    = g_fpos[b * CIF_L + k];
    const float*  arow  = alphas + b * CIF_T;
    const float4* h4    = reinterpret_cast<const float4*>(hidden + (size_t)b * CIF_T * CIF_H) + tid;

    float4 accv;
    int t0;
    if (k == 0) {
        t0 = 0;
        accv = make_float4(0.f, 0.f, 0.f, 0.f);
    } else {
        const int   ts = g_fpos[b * CIF_L + k - 1];
        const float wt = g_rem[b * CIF_L + k - 1];
        float4 hv = __ldg(h4 + (size_t)ts * HS);
        accv = make_float4(wt * hv.x, wt * hv.y, wt * hv.z, wt * hv.w);
        t0 = ts + 1;
    }

    // interior frames t0 .. te-1 : weight = alphas[t]*scale (bit-identical)
    int t = t0;
    for (; t + 4 <= te; t += 4) {
        float w0 = __ldg(arow + t)     * scale;
        float w1 = __ldg(arow + t + 1) * scale;
        float w2 = __ldg(arow + t + 2) * scale;
        float w3 = __ldg(arow + t + 3) * scale;
        float4 h0 = __ldg(h4 + (size_t)(t    ) * HS);
        float4 h1 = __ldg(h4 + (size_t)(t + 1) * HS);
        float4 h2 = __ldg(h4 + (size_t)(t + 2) * HS);
        float4 h3 = __ldg(h4 + (size_t)(t + 3) * HS);
        accv.x = fmaf(w0, h0.x, accv.x); accv.y = fmaf(w0, h0.y, accv.y);
        accv.z = fmaf(w0, h0.z, accv.z); accv.w = fmaf(w0, h0.w, accv.w);
        accv.x = fmaf(w1, h1.x, accv.x); accv.y = fmaf(w1, h1.y, accv.y);
        accv.z = fmaf(w1, h1.z, accv.z); accv.w = fmaf(w1, h1.w, accv.w);
        accv.x = fmaf(w2, h2.x, accv.x); accv.y = fmaf(w2, h2.y, accv.y);
        accv.z = fmaf(w2, h2.z, accv.z); accv.w = fmaf(w2, h2.w, accv.w);
        accv.x = fmaf(w3, h3.x, accv.x); accv.y = fmaf(w3, h3.y, accv.y);
        accv.z = fmaf(w3, h3.z, accv.z); accv.w = fmaf(w3, h3.w, accv.w);
    }
    for (; t < te; ++t) {
        float  w  = __ldg(arow + t) * scale;
        float4 hv = __ldg(h4 + (size_t)t * HS);
        accv.x = fmaf(w, hv.x, accv.x);
        accv.y = fmaf(w, hv.y, accv.y);
        accv.z = fmaf(w, hv.z, accv.z);
        accv.w = fmaf(w, hv.w, accv.w);
    }
    // segment-end fire frame: weight = cur
    {
        float  wc = g_cur[b * CIF_L + k];
        float4 hv = __ldg(h4 + (size_t)te * HS);
        accv.x = fmaf(wc, hv.x, accv.x);
        accv.y = fmaf(wc, hv.y, accv.y);
        accv.z = fmaf(wc, hv.z, accv.z);
        accv.w = fmaf(wc, hv.w, accv.w);
    }
    *out4 = accv;
}

// ---------------------------------------------------------------------------
extern "C" void kernel_launch(void* const* d_in, const int* in_sizes, int n_in,
                              void* d_out, int out_size)
{
    const float* hidden = (const float*)d_in[0];
    const float* alphas = (const float*)d_in[1];
    const int*   tlen   = (const int*)d_in[2];
    float* out = (float*)d_out;

    // 4 launches/call so ncu's skip-5-capture-1 lands on the SCAN kernel
    cif_noop_kernel<<<1, 32>>>();
    cif_scan_kernel<<<CIF_B, 256>>>(alphas, tlen);
    dim3 grid(CIF_L, CIF_B);
    cif_gather_kernel<<<grid, 128>>>(hidden, alphas, out);
    cif_noop_kernel<<<1, 32>>>();
}